// round 10
// baseline (speedup 1.0000x reference)
#include <cuda_runtime.h>
#include <cuda_bf16.h>
#include <cstdint>

#define BB 32
#define DD 640
#define MM 1024
#define TRI (DD*(DD+1)/2)
#define TEMPR (1.0f/(2.0f*DD*MM))
#define EPSV 1e-5f

#define NBL 5                 /* 640/128 tile blocks per dim */
#define NTILE (NBL*(NBL+1)/2) /* 15 upper-tri tiles */
#define NWORK (NTILE*BB)      /* 480 gram work units */
#define KC 32                 /* bf16 K per chunk; hi|lo packed -> 128B/row */
#define NCH (MM/KC)           /* 32 chunks */
#define GRAM_CTAS 296         /* 2 per SM x 148 SMs -- all co-resident */
#define OUT_UNITS ((DD/2)*BB) /* 10240 row-pair units */

// ---- device scratch (no runtime allocation) ----
__device__ __align__(256) __nv_bfloat16 g_hl[(size_t)BB*DD*2048];  // 83.9 MB
__device__ __align__(256) float g_dcov[(size_t)BB*DD*DD];          // upper tiles only
__device__ float g_diag[BB*DD];
__device__ float g_rspart[(size_t)BB*NBL*DD];
__device__ float g_rowsum[BB*DD];   // pre-scaled by 1/D
__device__ float g_tot[BB];         // pre-scaled by 1/D^2
__device__ int   g_work;            // work queue (reset by conv_diag)
__device__ int   g_bar1, g_bar2;    // grid barriers (reset by conv_diag)

// ---------------- baseline-PTX helpers ----------------
__device__ __forceinline__ uint32_t smem_u32(const void* p) {
    uint32_t a;
    asm("{ .reg .u64 t; cvta.to.shared.u64 t, %1; cvt.u32.u64 %0, t; }" : "=r"(a) : "l"(p));
    return a;
}
#define SW128(o) ((o) ^ (((o) >> 3) & 0x70))

#define CP_ASYNC16(dst, src) \
    asm volatile("cp.async.cg.shared.global [%0], [%1], 16;" :: "r"(dst), "l"(src) : "memory")
#define CP_COMMIT() asm volatile("cp.async.commit_group;" ::: "memory")
#define CP_WAIT1()  asm volatile("cp.async.wait_group 1;" ::: "memory")
#define CP_WAIT0()  asm volatile("cp.async.wait_group 0;" ::: "memory")

#define LDSM4(r, addr) \
    asm volatile("ldmatrix.sync.aligned.m8n8.x4.shared.b16 {%0,%1,%2,%3}, [%4];" \
                 : "=r"((r)[0]), "=r"((r)[1]), "=r"((r)[2]), "=r"((r)[3]) : "r"(addr))

#define MMA_BF16(c, a, b0, b1) \
    asm volatile("mma.sync.aligned.m16n8k16.row.col.f32.bf16.bf16.f32 " \
                 "{%0,%1,%2,%3}, {%4,%5,%6,%7}, {%8,%9}, {%0,%1,%2,%3};" \
                 : "+f"((c)[0]), "+f"((c)[1]), "+f"((c)[2]), "+f"((c)[3]) \
                 : "r"((a)[0]), "r"((a)[1]), "r"((a)[2]), "r"((a)[3]), "r"(b0), "r"(b1))

// ---------------------------------------------------------------------------
// Kernel 1: fp32 -> packed (hi|lo) bf16 + diag row-norms. One warp per row.
// Also resets the work-queue + barrier counters (stream-ordered before gram).
// ---------------------------------------------------------------------------
__global__ void conv_diag_kernel(const float* __restrict__ x) {
    if (blockIdx.x == 0 && threadIdx.x == 0) { g_work = 0; g_bar1 = 0; g_bar2 = 0; }
    int w = (blockIdx.x * blockDim.x + threadIdx.x) >> 5;
    int lane = threadIdx.x & 31;
    if (w >= BB * DD) return;
    const float4* row = reinterpret_cast<const float4*>(x + (size_t)w * MM);
    __nv_bfloat16* pr = g_hl + (size_t)w * 2048;
    float s = 0.f;
    #pragma unroll
    for (int m4 = lane; m4 < MM / 4; m4 += 32) {
        float4 v = row[m4];
        s += v.x*v.x + v.y*v.y + v.z*v.z + v.w*v.w;
        __nv_bfloat16 h0 = __float2bfloat16(v.x), h1 = __float2bfloat16(v.y);
        __nv_bfloat16 h2 = __float2bfloat16(v.z), h3 = __float2bfloat16(v.w);
        __nv_bfloat16 l0 = __float2bfloat16(v.x - __bfloat162float(h0));
        __nv_bfloat16 l1 = __float2bfloat16(v.y - __bfloat162float(h1));
        __nv_bfloat16 l2 = __float2bfloat16(v.z - __bfloat162float(h2));
        __nv_bfloat16 l3 = __float2bfloat16(v.w - __bfloat162float(h3));
        uint2 hp, lp;
        hp.x = ((uint32_t)__bfloat16_as_ushort(h1) << 16) | __bfloat16_as_ushort(h0);
        hp.y = ((uint32_t)__bfloat16_as_ushort(h3) << 16) | __bfloat16_as_ushort(h2);
        lp.x = ((uint32_t)__bfloat16_as_ushort(l1) << 16) | __bfloat16_as_ushort(l0);
        lp.y = ((uint32_t)__bfloat16_as_ushort(l3) << 16) | __bfloat16_as_ushort(l2);
        int col0 = m4 * 4;
        int kc = col0 >> 5, wi = col0 & 31;
        *reinterpret_cast<uint2*>(pr + kc * 64 + wi)      = hp;
        *reinterpret_cast<uint2*>(pr + kc * 64 + 32 + wi) = lp;
    }
    #pragma unroll
    for (int o = 16; o > 0; o >>= 1) s += __shfl_down_sync(0xffffffffu, s, o);
    if (lane == 0) g_diag[w] = s;
}

// ---------------------------------------------------------------------------
// Kernel 2 (fused persistent): gram -> grid barrier -> combine -> grid
// barrier -> centering/triu output. 296 CTAs, all co-resident.
// ---------------------------------------------------------------------------
#define STAGE_BYTES 32768
#define SMEM_BYTES  98304

__device__ __forceinline__ void load_tile_async(const __nv_bfloat16* src,
                                                uint32_t dst, int kc, int tid) {
    #pragma unroll
    for (int it = 0; it < 4; it++) {
        int idx = it * 256 + tid;           // 0..1023
        int row = idx >> 3, c16 = idx & 7;
        const char* s = (const char*)src + (size_t)row * 4096 + kc * 128 + c16 * 16;
        uint32_t off = (uint32_t)(row * 128 + c16 * 16);
        CP_ASYNC16(dst + SW128(off), s);
    }
}

__device__ __forceinline__ void grid_barrier(int* ctr, int tid) {
    __syncthreads();
    __threadfence();
    if (tid == 0) {
        atomicAdd(ctr, 1);
        while (*(volatile int*)ctr < GRAM_CTAS) __nanosleep(128);
    }
    __syncthreads();
    __threadfence();
}

__global__ __launch_bounds__(256, 2) void fused_kernel(float* __restrict__ out) {
    extern __shared__ __align__(1024) uint8_t smem[];
    uint32_t sb = smem_u32(smem);
    __shared__ float s_di[128], s_dj[128];
    __shared__ float csh[256];
    __shared__ int s_w;

    int tid = threadIdx.x;
    int wid = tid >> 5, lane = tid & 31;
    int wr = wid >> 2, wc = wid & 3;   // 2 x 4 warp grid; warp tile 64x32

    int a_row = lane & 15;
    int a_kb  = (lane >> 4) * 16;
    int b_row = ((lane >> 4) << 3) + (lane & 7);
    int b_kb  = ((lane >> 3) & 1) * 16;
    int qr = lane >> 2, qc = lane & 3;

    // ================== Phase 1: gram (work queue) ==================
    for (;;) {
        if (tid == 0) s_w = atomicAdd(&g_work, 1);
        __syncthreads();
        int wk = s_w;
        if (wk >= NWORK) break;
        int bb = wk / NTILE;
        int lin = wk % NTILE, ti = 0, rem = lin;
        while (rem >= NBL - ti) { rem -= NBL - ti; ti++; }
        int tj = ti + rem;
        bool isdiag = (ti == tj);
        int gi0 = ti * 128, gj0 = tj * 128;

        const __nv_bfloat16* pA = g_hl + (size_t)(bb * DD + gi0) * 2048;
        const __nv_bfloat16* pB = g_hl + (size_t)(bb * DD + gj0) * 2048;

        float acc[4][4][4];
        #pragma unroll
        for (int i = 0; i < 4; i++)
            #pragma unroll
            for (int j = 0; j < 4; j++)
                #pragma unroll
                for (int k = 0; k < 4; k++) acc[i][j][k] = 0.f;

        load_tile_async(pA, sb, 0, tid);
        if (!isdiag) load_tile_async(pB, sb + 16384, 0, tid);
        CP_COMMIT();
        load_tile_async(pA, sb + STAGE_BYTES, 1, tid);
        if (!isdiag) load_tile_async(pB, sb + STAGE_BYTES + 16384, 1, tid);
        CP_COMMIT();

        int slot = 0;
        for (int kc = 0; kc < NCH; kc++) {
            uint32_t cur = sb + (uint32_t)slot * STAGE_BYTES;
            CP_WAIT1();
            __syncthreads();
            if (kc + 2 < NCH) {
                int ns = slot + 2; if (ns >= 3) ns -= 3;
                uint32_t nxt = sb + (uint32_t)ns * STAGE_BYTES;
                load_tile_async(pA, nxt, kc + 2, tid);
                if (!isdiag) load_tile_async(pB, nxt + 16384, kc + 2, tid);
                CP_COMMIT();
            } else {
                CP_COMMIT();   // keep group count in lockstep
            }
            uint32_t Ab = cur;
            uint32_t Bb = isdiag ? cur : cur + 16384;
            #pragma unroll
            for (int ks = 0; ks < 2; ks++) {
                uint32_t bh[2][4], bl[2][4];
                #pragma unroll
                for (int n2 = 0; n2 < 2; n2++) {
                    uint32_t off = (uint32_t)((wc * 32 + n2 * 16 + b_row) * 128 + ks * 32 + b_kb);
                    LDSM4(bh[n2], Bb + SW128(off));
                    LDSM4(bl[n2], Bb + SW128(off + 64));
                }
                #pragma unroll
                for (int mtg = 0; mtg < 2; mtg++) {
                    uint32_t ah[2][4], al[2][4];
                    #pragma unroll
                    for (int m2 = 0; m2 < 2; m2++) {
                        int mt = mtg * 2 + m2;
                        uint32_t off = (uint32_t)((wr * 64 + mt * 16 + a_row) * 128 + ks * 32 + a_kb);
                        LDSM4(ah[m2], Ab + SW128(off));
                        LDSM4(al[m2], Ab + SW128(off + 64));
                    }
                    #pragma unroll
                    for (int m2 = 0; m2 < 2; m2++) {
                        int mt = mtg * 2 + m2;
                        #pragma unroll
                        for (int nt = 0; nt < 4; nt++) {
                            int n2 = nt >> 1, hb = (nt & 1) * 2;
                            float* c = acc[mt][nt];
                            MMA_BF16(c, ah[m2], bh[n2][hb], bh[n2][hb + 1]);
                            MMA_BF16(c, ah[m2], bl[n2][hb], bl[n2][hb + 1]);
                            MMA_BF16(c, al[m2], bh[n2][hb], bh[n2][hb + 1]);
                        }
                    }
                }
            }
            if (++slot >= 3) slot = 0;
        }
        CP_WAIT0();

        // ---- tile epilogue through stage[128][132] ----
        if (tid < 128) {
            s_di[tid] = g_diag[bb * DD + gi0 + tid];
            s_dj[tid] = g_diag[bb * DD + gj0 + tid];
        }
        __syncthreads();

        float* stage = reinterpret_cast<float*>(smem);   // [128][132]
        float* dcb = g_dcov + (size_t)bb * DD * DD;

        #pragma unroll
        for (int mt = 0; mt < 4; mt++) {
            int r0 = wr * 64 + mt * 16 + qr;
            float di0 = s_di[r0], di1 = s_di[r0 + 8];
            #pragma unroll
            for (int nt = 0; nt < 4; nt++) {
                int c0 = wc * 32 + nt * 8 + qc * 2;
                float dj0 = s_dj[c0], dj1 = s_dj[c0 + 1];
                float* c = acc[mt][nt];
                stage[r0 * 132 + c0]           = sqrtf(fmaf(TEMPR, fmaxf(di0 + dj0 - 2.f * c[0], 0.f), EPSV));
                stage[r0 * 132 + c0 + 1]       = sqrtf(fmaf(TEMPR, fmaxf(di0 + dj1 - 2.f * c[1], 0.f), EPSV));
                stage[(r0 + 8) * 132 + c0]     = sqrtf(fmaf(TEMPR, fmaxf(di1 + dj0 - 2.f * c[2], 0.f), EPSV));
                stage[(r0 + 8) * 132 + c0 + 1] = sqrtf(fmaf(TEMPR, fmaxf(di1 + dj1 - 2.f * c[3], 0.f), EPSV));
            }
        }
        __syncthreads();

        #pragma unroll
        for (int it = 0; it < 64; it++) {
            int idx = it * 256 + tid;
            int r = idx >> 7, cjj = idx & 127;
            dcb[(size_t)(gi0 + r) * DD + gj0 + cjj] = stage[r * 132 + cjj];
        }
        #pragma unroll
        for (int rr = 0; rr < 16; rr++) {
            int r = wid * 16 + rr;
            float s = stage[r * 132 + lane] + stage[r * 132 + lane + 32] +
                      stage[r * 132 + lane + 64] + stage[r * 132 + lane + 96];
            #pragma unroll
            for (int o = 16; o > 0; o >>= 1) s += __shfl_down_sync(0xffffffffu, s, o);
            if (lane == 0) g_rspart[((size_t)bb * NBL + tj) * DD + gi0 + r] = s;
        }
        if (!isdiag && tid < 128) {
            float s = 0.f;
            #pragma unroll 8
            for (int r = 0; r < 128; r++) s += stage[r * 132 + tid];
            g_rspart[((size_t)bb * NBL + ti) * DD + gj0 + tid] = s;
        }
        __syncthreads();   // smem reuse safety for next work unit
    }

    // ================== barrier 1, then combine ==================
    grid_barrier(&g_bar1, tid);

    if (blockIdx.x < BB) {
        int b = blockIdx.x;
        const float inv_d = 1.f / DD;
        float loc = 0.f;
        for (int i = tid; i < DD; i += 256) {
            float s = 0.f;
            #pragma unroll
            for (int t = 0; t < NBL; t++) s += g_rspart[((size_t)b * NBL + t) * DD + i];
            g_rowsum[b * DD + i] = s * inv_d;
            loc += s;
        }
        csh[tid] = loc;
        __syncthreads();
        #pragma unroll
        for (int o = 128; o > 0; o >>= 1) {
            if (tid < o) csh[tid] += csh[tid + o];
            __syncthreads();
        }
        if (tid == 0) g_tot[b] = csh[0] * (inv_d * inv_d);
    }

    // ================== barrier 2, then centering + triu out ==================
    grid_barrier(&g_bar2, tid);

    for (int u = blockIdx.x; u < OUT_UNITS; u += GRAM_CTAS) {
        int b = u / (DD / 2), p = u % (DD / 2);
        float tot = g_tot[b];
        #pragma unroll
        for (int h = 0; h < 2; h++) {
            int i = h ? (DD - 1 - p) : p;
            float si = g_rowsum[b * DD + i];
            const float* dcr = g_dcov + ((size_t)b * DD + i) * DD;
            size_t base = (size_t)b * TRI + (size_t)i * DD - ((size_t)i * (i - 1)) / 2 - i;
            for (int j = i + tid; j < DD; j += 256)
                out[base + j] = dcr[j] - si - g_rowsum[b * DD + j] + tot;
        }
    }
}

// ---------------------------------------------------------------------------
extern "C" void kernel_launch(void* const* d_in, const int* in_sizes, int n_in,
                              void* d_out, int out_size) {
    const float* x = (const float*)d_in[0];
    float* out = (float*)d_out;

    cudaFuncSetAttribute(fused_kernel,
                         cudaFuncAttributeMaxDynamicSharedMemorySize, SMEM_BYTES);

    conv_diag_kernel<<<(BB * DD) / 8, 256>>>(x);
    fused_kernel<<<GRAM_CTAS, 256, SMEM_BYTES>>>(out);
}

// round 12
// speedup vs baseline: 1.1504x; 1.1504x over previous
#include <cuda_runtime.h>
#include <cuda_bf16.h>
#include <cstdint>

#define BB 32
#define DD 640
#define MM 1024
#define TRI (DD*(DD+1)/2)
#define TEMPR (1.0f/(2.0f*DD*MM))
#define EPSV 1e-5f

#define NBL 5                 /* 640/128 tile blocks per dim */
#define NTILE (NBL*(NBL+1)/2) /* 15 upper-tri tiles */
#define KC 32                 /* bf16 K per chunk; hi|lo packed -> 128B/row */
#define NCH (MM/KC)           /* 32 chunks */

// ---- device scratch (no runtime allocation) ----
__device__ __align__(256) __nv_bfloat16 g_hl[(size_t)BB*DD*2048];  // 83.9 MB
__device__ __align__(256) float g_dcov[(size_t)BB*DD*DD];          // upper tiles only
__device__ float g_diag[BB*DD];
__device__ float g_rspart[(size_t)BB*NBL*DD];
__device__ float g_rowsum[BB*DD];   // pre-scaled by 1/D
__device__ float g_tot[BB];         // pre-scaled by 1/D^2

// ---------------- baseline-PTX helpers ----------------
__device__ __forceinline__ uint32_t smem_u32(const void* p) {
    uint32_t a;
    asm("{ .reg .u64 t; cvta.to.shared.u64 t, %1; cvt.u32.u64 %0, t; }" : "=r"(a) : "l"(p));
    return a;
}
#define SW128(o) ((o) ^ (((o) >> 3) & 0x70))

// d = { lo16 = cvt(lo), hi16 = cvt(hi) }
#define CVT2BF16(d, hi, lo) \
    asm("cvt.rn.bf16x2.f32 %0, %1, %2;" : "=r"(d) : "f"(hi), "f"(lo))

#define CP_ASYNC16(dst, src) \
    asm volatile("cp.async.cg.shared.global [%0], [%1], 16;" :: "r"(dst), "l"(src) : "memory")
#define CP_COMMIT() asm volatile("cp.async.commit_group;" ::: "memory")
#define CP_WAIT0()  asm volatile("cp.async.wait_group 0;" ::: "memory")

#define LDSM4(r, addr) \
    asm volatile("ldmatrix.sync.aligned.m8n8.x4.shared.b16 {%0,%1,%2,%3}, [%4];" \
                 : "=r"((r)[0]), "=r"((r)[1]), "=r"((r)[2]), "=r"((r)[3]) : "r"(addr))

#define MMA_BF16(c, a, b0, b1) \
    asm volatile("mma.sync.aligned.m16n8k16.row.col.f32.bf16.bf16.f32 " \
                 "{%0,%1,%2,%3}, {%4,%5,%6,%7}, {%8,%9}, {%0,%1,%2,%3};" \
                 : "+f"((c)[0]), "+f"((c)[1]), "+f"((c)[2]), "+f"((c)[3]) \
                 : "r"((a)[0]), "r"((a)[1]), "r"((a)[2]), "r"((a)[3]), "r"(b0), "r"(b1))

// ---------------------------------------------------------------------------
// Kernel 1: fp32 -> packed (hi|lo) bf16 + diag row-norms. One warp per row.
// bf16x2 cvt packs 2 floats/instr; hi recovered via bit ops (no 2nd cvt).
// ---------------------------------------------------------------------------
__global__ void conv_diag_kernel(const float* __restrict__ x) {
    int w = (blockIdx.x * blockDim.x + threadIdx.x) >> 5;
    int lane = threadIdx.x & 31;
    if (w >= BB * DD) return;
    const float4* row = reinterpret_cast<const float4*>(x + (size_t)w * MM);
    __nv_bfloat16* pr = g_hl + (size_t)w * 2048;
    float s = 0.f;
    #pragma unroll
    for (int m4 = lane; m4 < MM / 4; m4 += 32) {
        float4 v = row[m4];
        s += v.x*v.x + v.y*v.y + v.z*v.z + v.w*v.w;
        uint32_t hA, hB;
        CVT2BF16(hA, v.y, v.x);      // lo16=bf16(v.x), hi16=bf16(v.y)
        CVT2BF16(hB, v.w, v.z);
        float h0 = __uint_as_float(hA << 16);
        float h1 = __uint_as_float(hA & 0xFFFF0000u);
        float h2 = __uint_as_float(hB << 16);
        float h3 = __uint_as_float(hB & 0xFFFF0000u);
        uint32_t lA, lB;
        CVT2BF16(lA, v.y - h1, v.x - h0);
        CVT2BF16(lB, v.w - h3, v.z - h2);
        int col0 = m4 * 4;
        int kc = col0 >> 5, wi = col0 & 31;
        uint2 hp; hp.x = hA; hp.y = hB;
        uint2 lp; lp.x = lA; lp.y = lB;
        *reinterpret_cast<uint2*>(pr + kc * 64 + wi)      = hp;
        *reinterpret_cast<uint2*>(pr + kc * 64 + 32 + wi) = lp;
    }
    #pragma unroll
    for (int o = 16; o > 0; o >>= 1) s += __shfl_down_sync(0xffffffffu, s, o);
    if (lane == 0) g_diag[w] = s;
}

// ---------------------------------------------------------------------------
// Kernel 2: Gram via mma.sync bf16 (hi/lo, 3 PASS-MAJOR passes), 128x128
// tiles, KC=32 packed hi|lo rows, double-buffered cp.async, 2 CTAs/SM.
// ---------------------------------------------------------------------------
#define STAGE_BYTES 32768
#define SMEM_BYTES  65536

__device__ __forceinline__ void load_tile_async(const __nv_bfloat16* src,
                                                uint32_t dst, int kc, int tid) {
    #pragma unroll
    for (int it = 0; it < 4; it++) {
        int idx = it * 256 + tid;           // 0..1023
        int row = idx >> 3, c16 = idx & 7;
        const char* s = (const char*)src + (size_t)row * 4096 + kc * 128 + c16 * 16;
        uint32_t off = (uint32_t)(row * 128 + c16 * 16);
        CP_ASYNC16(dst + SW128(off), s);
    }
}

__global__ __launch_bounds__(256, 2) void gram_mma_kernel() {
    extern __shared__ __align__(1024) uint8_t smem[];
    uint32_t sb = smem_u32(smem);
    __shared__ float s_di[128], s_dj[128];

    int tid = threadIdx.x;
    int wid = tid >> 5, lane = tid & 31;
    int bb = blockIdx.y;

    int lin = blockIdx.x, ti = 0, rem = lin;
    while (rem >= NBL - ti) { rem -= NBL - ti; ti++; }
    int tj = ti + rem;
    bool isdiag = (ti == tj);
    int gi0 = ti * 128, gj0 = tj * 128;

    const __nv_bfloat16* pA = g_hl + (size_t)(bb * DD + gi0) * 2048;
    const __nv_bfloat16* pB = g_hl + (size_t)(bb * DD + gj0) * 2048;

    int wr = wid >> 2, wc = wid & 3;   // 2 x 4 warp grid; warp tile 64x32

    int a_row = lane & 15;
    int a_kb  = (lane >> 4) * 16;
    int b_row = ((lane >> 4) << 3) + (lane & 7);
    int b_kb  = ((lane >> 3) & 1) * 16;

    float acc[4][4][4];
    #pragma unroll
    for (int i = 0; i < 4; i++)
        #pragma unroll
        for (int j = 0; j < 4; j++)
            #pragma unroll
            for (int k = 0; k < 4; k++) acc[i][j][k] = 0.f;

    // preload chunk 0
    load_tile_async(pA, sb, 0, tid);
    if (!isdiag) load_tile_async(pB, sb + 16384, 0, tid);
    CP_COMMIT();

    for (int kc = 0; kc < NCH; kc++) {
        uint32_t cur = sb + (uint32_t)(kc & 1) * STAGE_BYTES;
        CP_WAIT0();
        __syncthreads();
        if (kc + 1 < NCH) {
            uint32_t nxt = sb + (uint32_t)((kc + 1) & 1) * STAGE_BYTES;
            load_tile_async(pA, nxt, kc + 1, tid);
            if (!isdiag) load_tile_async(pB, nxt + 16384, kc + 1, tid);
            CP_COMMIT();
        }
        uint32_t Ab = cur;
        uint32_t Bb = isdiag ? cur : cur + 16384;
        #pragma unroll
        for (int ks = 0; ks < 2; ks++) {
            uint32_t bh[2][4], bl[2][4];
            #pragma unroll
            for (int n2 = 0; n2 < 2; n2++) {
                uint32_t off = (uint32_t)((wc * 32 + n2 * 16 + b_row) * 128 + ks * 32 + b_kb);
                LDSM4(bh[n2], Bb + SW128(off));
                LDSM4(bl[n2], Bb + SW128(off + 64));
            }
            #pragma unroll
            for (int mtg = 0; mtg < 2; mtg++) {
                uint32_t ah[2][4], al[2][4];
                #pragma unroll
                for (int m2 = 0; m2 < 2; m2++) {
                    int mt = mtg * 2 + m2;
                    uint32_t off = (uint32_t)((wr * 64 + mt * 16 + a_row) * 128 + ks * 32 + a_kb);
                    LDSM4(ah[m2], Ab + SW128(off));
                    LDSM4(al[m2], Ab + SW128(off + 64));
                }
                // PASS-MAJOR: same-acc MMAs spaced 8 apart -> no RAW chains
                #pragma unroll
                for (int m2 = 0; m2 < 2; m2++)
                    #pragma unroll
                    for (int nt = 0; nt < 4; nt++) {
                        int n2 = nt >> 1, hb = (nt & 1) * 2;
                        MMA_BF16(acc[mtg * 2 + m2][nt], ah[m2], bh[n2][hb], bh[n2][hb + 1]);
                    }
                #pragma unroll
                for (int m2 = 0; m2 < 2; m2++)
                    #pragma unroll
                    for (int nt = 0; nt < 4; nt++) {
                        int n2 = nt >> 1, hb = (nt & 1) * 2;
                        MMA_BF16(acc[mtg * 2 + m2][nt], ah[m2], bl[n2][hb], bl[n2][hb + 1]);
                    }
                #pragma unroll
                for (int m2 = 0; m2 < 2; m2++)
                    #pragma unroll
                    for (int nt = 0; nt < 4; nt++) {
                        int n2 = nt >> 1, hb = (nt & 1) * 2;
                        MMA_BF16(acc[mtg * 2 + m2][nt], al[m2], bh[n2][hb], bh[n2][hb + 1]);
                    }
            }
        }
    }

    // ---- epilogue: two 64-row halves through stage[64][132] ----
    if (tid < 128) {
        s_di[tid] = g_diag[bb * DD + gi0 + tid];
        s_dj[tid] = g_diag[bb * DD + gj0 + tid];
    }
    __syncthreads();   // all warps done with pipeline smem

    float* stage = reinterpret_cast<float*>(smem);   // [64][132]
    float* dcb = g_dcov + (size_t)bb * DD * DD;
    int qr = lane >> 2, qc = lane & 3;
    float csum = 0.f;   // column partial (tid<128)

    #pragma unroll
    for (int h = 0; h < 2; h++) {
        if (wr == h) {
            #pragma unroll
            for (int mt = 0; mt < 4; mt++) {
                int rl = mt * 16 + qr;                 // local row 0..63
                float di0 = s_di[h * 64 + rl], di1 = s_di[h * 64 + rl + 8];
                #pragma unroll
                for (int nt = 0; nt < 4; nt++) {
                    int c0 = wc * 32 + nt * 8 + qc * 2;
                    float dj0 = s_dj[c0], dj1 = s_dj[c0 + 1];
                    float* c = acc[mt][nt];
                    stage[rl * 132 + c0]           = sqrtf(fmaf(TEMPR, fmaxf(di0 + dj0 - 2.f * c[0], 0.f), EPSV));
                    stage[rl * 132 + c0 + 1]       = sqrtf(fmaf(TEMPR, fmaxf(di0 + dj1 - 2.f * c[1], 0.f), EPSV));
                    stage[(rl + 8) * 132 + c0]     = sqrtf(fmaf(TEMPR, fmaxf(di1 + dj0 - 2.f * c[2], 0.f), EPSV));
                    stage[(rl + 8) * 132 + c0 + 1] = sqrtf(fmaf(TEMPR, fmaxf(di1 + dj1 - 2.f * c[3], 0.f), EPSV));
                }
            }
        }
        __syncthreads();

        // coalesced dcov store: 64 rows x 128 cols
        #pragma unroll
        for (int it = 0; it < 32; it++) {
            int idx = it * 256 + tid;
            int r = idx >> 7, cjj = idx & 127;
            dcb[(size_t)(gi0 + h * 64 + r) * DD + gj0 + cjj] = stage[r * 132 + cjj];
        }
        // row partial sums -> slot [tj]
        #pragma unroll
        for (int rr = 0; rr < 8; rr++) {
            int rl = wid * 8 + rr;
            float s = stage[rl * 132 + lane] + stage[rl * 132 + lane + 32] +
                      stage[rl * 132 + lane + 64] + stage[rl * 132 + lane + 96];
            #pragma unroll
            for (int o = 16; o > 0; o >>= 1) s += __shfl_down_sync(0xffffffffu, s, o);
            if (lane == 0)
                g_rspart[((size_t)bb * NBL + tj) * DD + gi0 + h * 64 + rl] = s;
        }
        // column partial accumulation (mirror), off-diagonal only
        if (!isdiag && tid < 128) {
            #pragma unroll 8
            for (int r = 0; r < 64; r++) csum += stage[r * 132 + tid];
        }
        __syncthreads();
    }
    if (!isdiag && tid < 128)
        g_rspart[((size_t)bb * NBL + ti) * DD + gj0 + tid] = csum;
}

// ---------------------------------------------------------------------------
// Kernel 3: combine partials -> rowsum/D + tot/D^2 (deterministic)
// ---------------------------------------------------------------------------
__global__ void combine_kernel() {
    int b = blockIdx.x;
    __shared__ float sh[256];
    const float inv_d = 1.f / DD;
    float loc = 0.f;
    for (int i = threadIdx.x; i < DD; i += 256) {
        float s = 0.f;
        #pragma unroll
        for (int t = 0; t < NBL; t++) s += g_rspart[((size_t)b * NBL + t) * DD + i];
        g_rowsum[b * DD + i] = s * inv_d;
        loc += s;
    }
    sh[threadIdx.x] = loc;
    __syncthreads();
    #pragma unroll
    for (int o = 128; o > 0; o >>= 1) {
        if (threadIdx.x < o) sh[threadIdx.x] += sh[threadIdx.x + o];
        __syncthreads();
    }
    if (threadIdx.x == 0) g_tot[b] = sh[0] * (inv_d * inv_d);
}

// ---------------------------------------------------------------------------
// Kernel 4: centering + triu gather; rows paired (p, 639-p) for balance.
// (R7 version -- best measured: 21.0us)
// ---------------------------------------------------------------------------
__global__ void out_kernel(float* __restrict__ out) {
    int p = blockIdx.x;     // 0..319
    int b = blockIdx.y;
    float tot = g_tot[b];
    #pragma unroll
    for (int h = 0; h < 2; h++) {
        int i = h ? (DD - 1 - p) : p;
        float si = g_rowsum[b * DD + i];
        const float* dcr = g_dcov + ((size_t)b * DD + i) * DD;
        size_t base = (size_t)b * TRI + (size_t)i * DD - ((size_t)i * (i - 1)) / 2 - i;
        for (int j = i + threadIdx.x; j < DD; j += 256)
            out[base + j] = dcr[j] - si - g_rowsum[b * DD + j] + tot;
    }
}

// ---------------------------------------------------------------------------
extern "C" void kernel_launch(void* const* d_in, const int* in_sizes, int n_in,
                              void* d_out, int out_size) {
    const float* x = (const float*)d_in[0];
    float* out = (float*)d_out;

    cudaFuncSetAttribute(gram_mma_kernel,
                         cudaFuncAttributeMaxDynamicSharedMemorySize, SMEM_BYTES);

    conv_diag_kernel<<<(BB * DD) / 8, 256>>>(x);
    gram_mma_kernel<<<dim3(NTILE, BB), 256, SMEM_BYTES>>>();
    combine_kernel<<<BB, 256>>>();
    out_kernel<<<dim3(DD / 2, BB), 256>>>(out);
}

// round 14
// speedup vs baseline: 1.3608x; 1.1829x over previous
#include <cuda_runtime.h>
#include <cuda_bf16.h>
#include <cstdint>

#define BB 32
#define DD 640
#define MM 1024
#define TRI (DD*(DD+1)/2)
#define TEMPR (1.0f/(2.0f*DD*MM))
#define EPSV 1e-5f

#define NBL 10                /* 640/64 tile blocks per dim */
#define NTILE (NBL*(NBL+1)/2) /* 55 upper-tri tiles per batch */
#define KC 32                 /* bf16 K per chunk; hi|lo packed -> 128B/row */
#define NCH (MM/KC)           /* 32 chunks */

// ---- device scratch (no runtime allocation) ----
__device__ __align__(256) __nv_bfloat16 g_hl[(size_t)BB*DD*2048];  // 83.9 MB
__device__ __align__(256) float g_dcov[(size_t)BB*DD*DD];          // upper tiles only
__device__ float g_diag[BB*DD];
__device__ float g_rspart[(size_t)BB*NBL*DD];
__device__ float g_rowsum[BB*DD];   // pre-scaled by 1/D
__device__ float g_tot[BB];         // pre-scaled by 1/D^2

// ---------------- baseline-PTX helpers ----------------
__device__ __forceinline__ uint32_t smem_u32(const void* p) {
    uint32_t a;
    asm("{ .reg .u64 t; cvta.to.shared.u64 t, %1; cvt.u32.u64 %0, t; }" : "=r"(a) : "l"(p));
    return a;
}
#define SW128(o) ((o) ^ (((o) >> 3) & 0x70))

// d = { lo16 = cvt(lo), hi16 = cvt(hi) }
#define CVT2BF16(d, hi, lo) \
    asm("cvt.rn.bf16x2.f32 %0, %1, %2;" : "=r"(d) : "f"(hi), "f"(lo))

#define CP_ASYNC16(dst, src) \
    asm volatile("cp.async.cg.shared.global [%0], [%1], 16;" :: "r"(dst), "l"(src) : "memory")
#define CP_COMMIT() asm volatile("cp.async.commit_group;" ::: "memory")
#define CP_WAIT0()  asm volatile("cp.async.wait_group 0;" ::: "memory")

#define LDSM4(r, addr) \
    asm volatile("ldmatrix.sync.aligned.m8n8.x4.shared.b16 {%0,%1,%2,%3}, [%4];" \
                 : "=r"((r)[0]), "=r"((r)[1]), "=r"((r)[2]), "=r"((r)[3]) : "r"(addr))

#define MMA_BF16(c, a, b0, b1) \
    asm volatile("mma.sync.aligned.m16n8k16.row.col.f32.bf16.bf16.f32 " \
                 "{%0,%1,%2,%3}, {%4,%5,%6,%7}, {%8,%9}, {%0,%1,%2,%3};" \
                 : "+f"((c)[0]), "+f"((c)[1]), "+f"((c)[2]), "+f"((c)[3]) \
                 : "r"((a)[0]), "r"((a)[1]), "r"((a)[2]), "r"((a)[3]), "r"(b0), "r"(b1))

// ---------------------------------------------------------------------------
// Kernel 1: fp32 -> packed (hi|lo) bf16 + diag row-norms. One warp per row.
// ---------------------------------------------------------------------------
__global__ void conv_diag_kernel(const float* __restrict__ x) {
    int w = (blockIdx.x * blockDim.x + threadIdx.x) >> 5;
    int lane = threadIdx.x & 31;
    if (w >= BB * DD) return;
    const float4* row = reinterpret_cast<const float4*>(x + (size_t)w * MM);
    __nv_bfloat16* pr = g_hl + (size_t)w * 2048;
    float s = 0.f;
    #pragma unroll
    for (int m4 = lane; m4 < MM / 4; m4 += 32) {
        float4 v = row[m4];
        s += v.x*v.x + v.y*v.y + v.z*v.z + v.w*v.w;
        uint32_t hA, hB;
        CVT2BF16(hA, v.y, v.x);
        CVT2BF16(hB, v.w, v.z);
        float h0 = __uint_as_float(hA << 16);
        float h1 = __uint_as_float(hA & 0xFFFF0000u);
        float h2 = __uint_as_float(hB << 16);
        float h3 = __uint_as_float(hB & 0xFFFF0000u);
        uint32_t lA, lB;
        CVT2BF16(lA, v.y - h1, v.x - h0);
        CVT2BF16(lB, v.w - h3, v.z - h2);
        int col0 = m4 * 4;
        int kc = col0 >> 5, wi = col0 & 31;
        uint2 hp; hp.x = hA; hp.y = hB;
        uint2 lp; lp.x = lA; lp.y = lB;
        *reinterpret_cast<uint2*>(pr + kc * 64 + wi)      = hp;
        *reinterpret_cast<uint2*>(pr + kc * 64 + 32 + wi) = lp;
    }
    #pragma unroll
    for (int o = 16; o > 0; o >>= 1) s += __shfl_down_sync(0xffffffffu, s, o);
    if (lane == 0) g_diag[w] = s;
}

// ---------------------------------------------------------------------------
// Kernel 2: Gram via mma.sync bf16 (hi/lo, 3 passes), 64x64 tiles, 4-warp
// CTAs, double-buffered cp.async, 5 CTAs/SM (phase-decorrelated warps).
// ---------------------------------------------------------------------------
// smem: two 16KB stages (A 8K @0, B 8K @8192). Epilogue reuses as
// float stage[64][68] (17.4KB <= 32KB).
#define STAGE_BYTES 16384
#define SMEM_BYTES  32768

__device__ __forceinline__ void load_tile64(const __nv_bfloat16* src,
                                            uint32_t dst, int kc, int tid) {
    #pragma unroll
    for (int it = 0; it < 4; it++) {
        int idx = it * 128 + tid;           // 0..511
        int row = idx >> 3, c16 = idx & 7;  // 64 rows x 8 sixteens
        const char* s = (const char*)src + (size_t)row * 4096 + kc * 128 + c16 * 16;
        uint32_t off = (uint32_t)(row * 128 + c16 * 16);
        CP_ASYNC16(dst + SW128(off), s);
    }
}

__global__ __launch_bounds__(128, 5) void gram_mma_kernel() {
    extern __shared__ __align__(1024) uint8_t smem[];
    uint32_t sb = smem_u32(smem);
    __shared__ float s_di[64], s_dj[64];

    int tid = threadIdx.x;
    int wid = tid >> 5, lane = tid & 31;
    int bb = blockIdx.y;

    int lin = blockIdx.x, ti = 0, rem = lin;
    while (rem >= NBL - ti) { rem -= NBL - ti; ti++; }
    int tj = ti + rem;
    bool isdiag = (ti == tj);
    int gi0 = ti * 64, gj0 = tj * 64;

    const __nv_bfloat16* pA = g_hl + (size_t)(bb * DD + gi0) * 2048;
    const __nv_bfloat16* pB = g_hl + (size_t)(bb * DD + gj0) * 2048;

    int wr = wid >> 1, wc = wid & 1;   // 2 x 2 warp grid; warp tile 32x32

    int a_row = lane & 15;
    int a_kb  = (lane >> 4) * 16;
    int b_row = ((lane >> 4) << 3) + (lane & 7);
    int b_kb  = ((lane >> 3) & 1) * 16;

    float acc[2][4][4];
    #pragma unroll
    for (int i = 0; i < 2; i++)
        #pragma unroll
        for (int j = 0; j < 4; j++)
            #pragma unroll
            for (int k = 0; k < 4; k++) acc[i][j][k] = 0.f;

    // preload chunk 0
    load_tile64(pA, sb, 0, tid);
    if (!isdiag) load_tile64(pB, sb + 8192, 0, tid);
    CP_COMMIT();

    for (int kc = 0; kc < NCH; kc++) {
        uint32_t cur = sb + (uint32_t)(kc & 1) * STAGE_BYTES;
        CP_WAIT0();
        __syncthreads();
        if (kc + 1 < NCH) {
            uint32_t nxt = sb + (uint32_t)((kc + 1) & 1) * STAGE_BYTES;
            load_tile64(pA, nxt, kc + 1, tid);
            if (!isdiag) load_tile64(pB, nxt + 8192, kc + 1, tid);
            CP_COMMIT();
        }
        uint32_t Ab = cur;
        uint32_t Bb = isdiag ? cur : cur + 8192;
        #pragma unroll
        for (int ks = 0; ks < 2; ks++) {
            uint32_t bh[2][4], bl[2][4], ah[2][4], al[2][4];
            #pragma unroll
            for (int n2 = 0; n2 < 2; n2++) {
                uint32_t off = (uint32_t)((wc * 32 + n2 * 16 + b_row) * 128 + ks * 32 + b_kb);
                LDSM4(bh[n2], Bb + SW128(off));
                LDSM4(bl[n2], Bb + SW128(off + 64));
            }
            #pragma unroll
            for (int mt = 0; mt < 2; mt++) {
                uint32_t off = (uint32_t)((wr * 32 + mt * 16 + a_row) * 128 + ks * 32 + a_kb);
                LDSM4(ah[mt], Ab + SW128(off));
                LDSM4(al[mt], Ab + SW128(off + 64));
            }
            // pass-major: hi*hi, hi*lo, lo*hi
            #pragma unroll
            for (int mt = 0; mt < 2; mt++)
                #pragma unroll
                for (int nt = 0; nt < 4; nt++) {
                    int n2 = nt >> 1, hb = (nt & 1) * 2;
                    MMA_BF16(acc[mt][nt], ah[mt], bh[n2][hb], bh[n2][hb + 1]);
                }
            #pragma unroll
            for (int mt = 0; mt < 2; mt++)
                #pragma unroll
                for (int nt = 0; nt < 4; nt++) {
                    int n2 = nt >> 1, hb = (nt & 1) * 2;
                    MMA_BF16(acc[mt][nt], ah[mt], bl[n2][hb], bl[n2][hb + 1]);
                }
            #pragma unroll
            for (int mt = 0; mt < 2; mt++)
                #pragma unroll
                for (int nt = 0; nt < 4; nt++) {
                    int n2 = nt >> 1, hb = (nt & 1) * 2;
                    MMA_BF16(acc[mt][nt], al[mt], bh[n2][hb], bh[n2][hb + 1]);
                }
        }
    }

    // ---- epilogue through stage[64][68] ----
    if (tid < 64) {
        s_di[tid] = g_diag[bb * DD + gi0 + tid];
        s_dj[tid] = g_diag[bb * DD + gj0 + tid];
    }
    __syncthreads();   // all warps done with pipeline smem

    float* stage = reinterpret_cast<float*>(smem);   // [64][68]
    float* dcb = g_dcov + (size_t)bb * DD * DD;
    int qr = lane >> 2, qc = lane & 3;

    #pragma unroll
    for (int mt = 0; mt < 2; mt++) {
        int r0 = wr * 32 + mt * 16 + qr;
        float di0 = s_di[r0], di1 = s_di[r0 + 8];
        #pragma unroll
        for (int nt = 0; nt < 4; nt++) {
            int c0 = wc * 32 + nt * 8 + qc * 2;
            float dj0 = s_dj[c0], dj1 = s_dj[c0 + 1];
            float* c = acc[mt][nt];
            stage[r0 * 68 + c0]           = sqrtf(fmaf(TEMPR, fmaxf(di0 + dj0 - 2.f * c[0], 0.f), EPSV));
            stage[r0 * 68 + c0 + 1]       = sqrtf(fmaf(TEMPR, fmaxf(di0 + dj1 - 2.f * c[1], 0.f), EPSV));
            stage[(r0 + 8) * 68 + c0]     = sqrtf(fmaf(TEMPR, fmaxf(di1 + dj0 - 2.f * c[2], 0.f), EPSV));
            stage[(r0 + 8) * 68 + c0 + 1] = sqrtf(fmaf(TEMPR, fmaxf(di1 + dj1 - 2.f * c[3], 0.f), EPSV));
        }
    }
    __syncthreads();

    // coalesced dcov store: 64 x 64
    #pragma unroll
    for (int it = 0; it < 32; it++) {
        int idx = it * 128 + tid;
        int r = idx >> 6, cjj = idx & 63;
        dcb[(size_t)(gi0 + r) * DD + gj0 + cjj] = stage[r * 68 + cjj];
    }
    // row partial sums -> slot [tj]
    #pragma unroll
    for (int rr = 0; rr < 16; rr++) {
        int r = wid * 16 + rr;
        float s = stage[r * 68 + lane] + stage[r * 68 + lane + 32];
        #pragma unroll
        for (int o = 16; o > 0; o >>= 1) s += __shfl_down_sync(0xffffffffu, s, o);
        if (lane == 0) g_rspart[((size_t)bb * NBL + tj) * DD + gi0 + r] = s;
    }
    // column partial sums (mirror), off-diagonal only
    if (!isdiag && tid < 64) {
        float s = 0.f;
        #pragma unroll 8
        for (int r = 0; r < 64; r++) s += stage[r * 68 + tid];
        g_rspart[((size_t)bb * NBL + ti) * DD + gj0 + tid] = s;
    }
}

// ---------------------------------------------------------------------------
// Kernel 3: combine partials -> rowsum/D + tot/D^2 (deterministic)
// ---------------------------------------------------------------------------
__global__ void combine_kernel() {
    int b = blockIdx.x;
    __shared__ float sh[256];
    const float inv_d = 1.f / DD;
    float loc = 0.f;
    for (int i = threadIdx.x; i < DD; i += 256) {
        float s = 0.f;
        #pragma unroll
        for (int t = 0; t < NBL; t++) s += g_rspart[((size_t)b * NBL + t) * DD + i];
        g_rowsum[b * DD + i] = s * inv_d;
        loc += s;
    }
    sh[threadIdx.x] = loc;
    __syncthreads();
    #pragma unroll
    for (int o = 128; o > 0; o >>= 1) {
        if (threadIdx.x < o) sh[threadIdx.x] += sh[threadIdx.x + o];
        __syncthreads();
    }
    if (threadIdx.x == 0) g_tot[b] = sh[0] * (inv_d * inv_d);
}

// ---------------------------------------------------------------------------
// Kernel 4: centering + triu gather; rows paired (p, 639-p), unroll-2 MLP.
// ---------------------------------------------------------------------------
__global__ void out_kernel(float* __restrict__ out) {
    int p = blockIdx.x;     // 0..319
    int b = blockIdx.y;
    float tot = g_tot[b];
    const float* rs = g_rowsum + b * DD;
    #pragma unroll
    for (int h = 0; h < 2; h++) {
        int i = h ? (DD - 1 - p) : p;
        float si = tot - rs[i];
        const float* dcr = g_dcov + ((size_t)b * DD + i) * DD;
        size_t base = (size_t)b * TRI + (size_t)i * DD - ((size_t)i * (i - 1)) / 2 - i;
        for (int j = i + threadIdx.x; j < DD; j += 512) {
            int j2 = j + 256;
            float d0 = dcr[j], r0 = rs[j];
            float d1 = 0.f, r1 = 0.f;
            bool ok = (j2 < DD);
            if (ok) { d1 = dcr[j2]; r1 = rs[j2]; }
            out[base + j] = d0 - r0 + si;
            if (ok) out[base + j2] = d1 - r1 + si;
        }
    }
}

// ---------------------------------------------------------------------------
extern "C" void kernel_launch(void* const* d_in, const int* in_sizes, int n_in,
                              void* d_out, int out_size) {
    const float* x = (const float*)d_in[0];
    float* out = (float*)d_out;

    cudaFuncSetAttribute(gram_mma_kernel,
                         cudaFuncAttributeMaxDynamicSharedMemorySize, SMEM_BYTES);

    conv_diag_kernel<<<(BB * DD) / 8, 256>>>(x);
    gram_mma_kernel<<<dim3(NTILE, BB), 128, SMEM_BYTES>>>();
    combine_kernel<<<BB, 256>>>();
    out_kernel<<<dim3(DD / 2, BB), 256>>>(out);
}

// round 15
// speedup vs baseline: 1.3701x; 1.0068x over previous
#include <cuda_runtime.h>
#include <cuda_bf16.h>
#include <cstdint>

#define BB 32
#define DD 640
#define MM 1024
#define TRI (DD*(DD+1)/2)
#define TEMPR (1.0f/(2.0f*DD*MM))
#define EPSV 1e-5f

#define NBL 10                /* 640/64 tile blocks per dim */
#define NTILE (NBL*(NBL+1)/2) /* 55 upper-tri tiles per batch */
#define KC 32                 /* bf16 K per chunk; hi|lo packed -> 128B/row */
#define NCH (MM/KC)           /* 32 chunks */

// ---- device scratch (no runtime allocation) ----
__device__ __align__(256) __nv_bfloat16 g_hl[(size_t)BB*DD*2048];  // 83.9 MB
__device__ __align__(256) float g_dcov[(size_t)BB*DD*DD];          // upper tiles only
__device__ float g_diag[BB*DD];
__device__ float g_rspart[(size_t)BB*NBL*DD];
__device__ float g_rowsum[BB*DD];   // pre-scaled by 1/D
__device__ float g_tot[BB];         // pre-scaled by 1/D^2

// ---------------- baseline-PTX helpers ----------------
__device__ __forceinline__ uint32_t smem_u32(const void* p) {
    uint32_t a;
    asm("{ .reg .u64 t; cvta.to.shared.u64 t, %1; cvt.u32.u64 %0, t; }" : "=r"(a) : "l"(p));
    return a;
}
#define SW128(o) ((o) ^ (((o) >> 3) & 0x70))

// d = { lo16 = cvt(lo), hi16 = cvt(hi) }
#define CVT2BF16(d, hi, lo) \
    asm("cvt.rn.bf16x2.f32 %0, %1, %2;" : "=r"(d) : "f"(hi), "f"(lo))

#define CP_ASYNC16(dst, src) \
    asm volatile("cp.async.cg.shared.global [%0], [%1], 16;" :: "r"(dst), "l"(src) : "memory")
#define CP_COMMIT() asm volatile("cp.async.commit_group;" ::: "memory")
#define CP_WAIT0()  asm volatile("cp.async.wait_group 0;" ::: "memory")

#define LDSM4(r, addr) \
    asm volatile("ldmatrix.sync.aligned.m8n8.x4.shared.b16 {%0,%1,%2,%3}, [%4];" \
                 : "=r"((r)[0]), "=r"((r)[1]), "=r"((r)[2]), "=r"((r)[3]) : "r"(addr))

#define MMA_BF16(c, a, b0, b1) \
    asm volatile("mma.sync.aligned.m16n8k16.row.col.f32.bf16.bf16.f32 " \
                 "{%0,%1,%2,%3}, {%4,%5,%6,%7}, {%8,%9}, {%0,%1,%2,%3};" \
                 : "+f"((c)[0]), "+f"((c)[1]), "+f"((c)[2]), "+f"((c)[3]) \
                 : "r"((a)[0]), "r"((a)[1]), "r"((a)[2]), "r"((a)[3]), "r"(b0), "r"(b1))

// ---------------------------------------------------------------------------
// Kernel 1: fp32 -> packed (hi|lo) bf16 + diag row-norms. One warp per row.
// ---------------------------------------------------------------------------
__global__ void conv_diag_kernel(const float* __restrict__ x) {
    int w = (blockIdx.x * blockDim.x + threadIdx.x) >> 5;
    int lane = threadIdx.x & 31;
    if (w >= BB * DD) return;
    const float4* row = reinterpret_cast<const float4*>(x + (size_t)w * MM);
    __nv_bfloat16* pr = g_hl + (size_t)w * 2048;
    float s = 0.f;
    #pragma unroll
    for (int m4 = lane; m4 < MM / 4; m4 += 32) {
        float4 v = row[m4];
        s += v.x*v.x + v.y*v.y + v.z*v.z + v.w*v.w;
        uint32_t hA, hB;
        CVT2BF16(hA, v.y, v.x);
        CVT2BF16(hB, v.w, v.z);
        float h0 = __uint_as_float(hA << 16);
        float h1 = __uint_as_float(hA & 0xFFFF0000u);
        float h2 = __uint_as_float(hB << 16);
        float h3 = __uint_as_float(hB & 0xFFFF0000u);
        uint32_t lA, lB;
        CVT2BF16(lA, v.y - h1, v.x - h0);
        CVT2BF16(lB, v.w - h3, v.z - h2);
        int col0 = m4 * 4;
        int kc = col0 >> 5, wi = col0 & 31;
        uint2 hp; hp.x = hA; hp.y = hB;
        uint2 lp; lp.x = lA; lp.y = lB;
        *reinterpret_cast<uint2*>(pr + kc * 64 + wi)      = hp;
        *reinterpret_cast<uint2*>(pr + kc * 64 + 32 + wi) = lp;
    }
    #pragma unroll
    for (int o = 16; o > 0; o >>= 1) s += __shfl_down_sync(0xffffffffu, s, o);
    if (lane == 0) g_diag[w] = s;
}

// ---------------------------------------------------------------------------
// Kernel 2: Gram via mma.sync bf16 (hi/lo, 3 passes), 64x64 tiles, 4-warp
// CTAs, double-buffered cp.async, 6 CTAs/SM (phase-decorrelated warps).
// ---------------------------------------------------------------------------
// smem: two 16KB stages (A 8K @0, B 8K @8192). Epilogue reuses as
// float stage[64][68] (17.4KB <= 32KB).
#define STAGE_BYTES 16384
#define SMEM_BYTES  32768

__device__ __forceinline__ void load_tile64(const __nv_bfloat16* src,
                                            uint32_t dst, int kc, int tid) {
    #pragma unroll
    for (int it = 0; it < 4; it++) {
        int idx = it * 128 + tid;           // 0..511
        int row = idx >> 3, c16 = idx & 7;  // 64 rows x 8 sixteens
        const char* s = (const char*)src + (size_t)row * 4096 + kc * 128 + c16 * 16;
        uint32_t off = (uint32_t)(row * 128 + c16 * 16);
        CP_ASYNC16(dst + SW128(off), s);
    }
}

__global__ __launch_bounds__(128, 6) void gram_mma_kernel() {
    extern __shared__ __align__(1024) uint8_t smem[];
    uint32_t sb = smem_u32(smem);
    __shared__ float s_di[64], s_dj[64];

    int tid = threadIdx.x;
    int wid = tid >> 5, lane = tid & 31;
    int bb = blockIdx.y;

    int lin = blockIdx.x, ti = 0, rem = lin;
    while (rem >= NBL - ti) { rem -= NBL - ti; ti++; }
    int tj = ti + rem;
    bool isdiag = (ti == tj);
    int gi0 = ti * 64, gj0 = tj * 64;

    const __nv_bfloat16* pA = g_hl + (size_t)(bb * DD + gi0) * 2048;
    const __nv_bfloat16* pB = g_hl + (size_t)(bb * DD + gj0) * 2048;

    int wr = wid >> 1, wc = wid & 1;   // 2 x 2 warp grid; warp tile 32x32

    int a_row = lane & 15;
    int a_kb  = (lane >> 4) * 16;
    int b_row = ((lane >> 4) << 3) + (lane & 7);
    int b_kb  = ((lane >> 3) & 1) * 16;

    float acc[2][4][4];
    #pragma unroll
    for (int i = 0; i < 2; i++)
        #pragma unroll
        for (int j = 0; j < 4; j++)
            #pragma unroll
            for (int k = 0; k < 4; k++) acc[i][j][k] = 0.f;

    // preload chunk 0
    load_tile64(pA, sb, 0, tid);
    if (!isdiag) load_tile64(pB, sb + 8192, 0, tid);
    CP_COMMIT();

    for (int kc = 0; kc < NCH; kc++) {
        uint32_t cur = sb + (uint32_t)(kc & 1) * STAGE_BYTES;
        CP_WAIT0();
        __syncthreads();
        if (kc + 1 < NCH) {
            uint32_t nxt = sb + (uint32_t)((kc + 1) & 1) * STAGE_BYTES;
            load_tile64(pA, nxt, kc + 1, tid);
            if (!isdiag) load_tile64(pB, nxt + 8192, kc + 1, tid);
            CP_COMMIT();
        }
        uint32_t Ab = cur;
        uint32_t Bb = isdiag ? cur : cur + 8192;
        #pragma unroll
        for (int ks = 0; ks < 2; ks++) {
            uint32_t bh[2][4], bl[2][4], ah[2][4], al[2][4];
            #pragma unroll
            for (int n2 = 0; n2 < 2; n2++) {
                uint32_t off = (uint32_t)((wc * 32 + n2 * 16 + b_row) * 128 + ks * 32 + b_kb);
                LDSM4(bh[n2], Bb + SW128(off));
                LDSM4(bl[n2], Bb + SW128(off + 64));
            }
            #pragma unroll
            for (int mt = 0; mt < 2; mt++) {
                uint32_t off = (uint32_t)((wr * 32 + mt * 16 + a_row) * 128 + ks * 32 + a_kb);
                LDSM4(ah[mt], Ab + SW128(off));
                LDSM4(al[mt], Ab + SW128(off + 64));
            }
            // pass-major: hi*hi, hi*lo, lo*hi
            #pragma unroll
            for (int mt = 0; mt < 2; mt++)
                #pragma unroll
                for (int nt = 0; nt < 4; nt++) {
                    int n2 = nt >> 1, hb = (nt & 1) * 2;
                    MMA_BF16(acc[mt][nt], ah[mt], bh[n2][hb], bh[n2][hb + 1]);
                }
            #pragma unroll
            for (int mt = 0; mt < 2; mt++)
                #pragma unroll
                for (int nt = 0; nt < 4; nt++) {
                    int n2 = nt >> 1, hb = (nt & 1) * 2;
                    MMA_BF16(acc[mt][nt], ah[mt], bl[n2][hb], bl[n2][hb + 1]);
                }
            #pragma unroll
            for (int mt = 0; mt < 2; mt++)
                #pragma unroll
                for (int nt = 0; nt < 4; nt++) {
                    int n2 = nt >> 1, hb = (nt & 1) * 2;
                    MMA_BF16(acc[mt][nt], al[mt], bh[n2][hb], bh[n2][hb + 1]);
                }
        }
    }

    // ---- epilogue through stage[64][68] ----
    if (tid < 64) {
        s_di[tid] = g_diag[bb * DD + gi0 + tid];
        s_dj[tid] = g_diag[bb * DD + gj0 + tid];
    }
    __syncthreads();   // all warps done with pipeline smem

    float* stage = reinterpret_cast<float*>(smem);   // [64][68]
    float* dcb = g_dcov + (size_t)bb * DD * DD;
    int qr = lane >> 2, qc = lane & 3;

    #pragma unroll
    for (int mt = 0; mt < 2; mt++) {
        int r0 = wr * 32 + mt * 16 + qr;
        float di0 = s_di[r0], di1 = s_di[r0 + 8];
        #pragma unroll
        for (int nt = 0; nt < 4; nt++) {
            int c0 = wc * 32 + nt * 8 + qc * 2;
            float dj0 = s_dj[c0], dj1 = s_dj[c0 + 1];
            float* c = acc[mt][nt];
            stage[r0 * 68 + c0]           = sqrtf(fmaf(TEMPR, fmaxf(di0 + dj0 - 2.f * c[0], 0.f), EPSV));
            stage[r0 * 68 + c0 + 1]       = sqrtf(fmaf(TEMPR, fmaxf(di0 + dj1 - 2.f * c[1], 0.f), EPSV));
            stage[(r0 + 8) * 68 + c0]     = sqrtf(fmaf(TEMPR, fmaxf(di1 + dj0 - 2.f * c[2], 0.f), EPSV));
            stage[(r0 + 8) * 68 + c0 + 1] = sqrtf(fmaf(TEMPR, fmaxf(di1 + dj1 - 2.f * c[3], 0.f), EPSV));
        }
    }
    __syncthreads();

    // coalesced dcov store: 64 x 64
    #pragma unroll
    for (int it = 0; it < 32; it++) {
        int idx = it * 128 + tid;
        int r = idx >> 6, cjj = idx & 63;
        dcb[(size_t)(gi0 + r) * DD + gj0 + cjj] = stage[r * 68 + cjj];
    }
    // row partial sums -> slot [tj]
    #pragma unroll
    for (int rr = 0; rr < 16; rr++) {
        int r = wid * 16 + rr;
        float s = stage[r * 68 + lane] + stage[r * 68 + lane + 32];
        #pragma unroll
        for (int o = 16; o > 0; o >>= 1) s += __shfl_down_sync(0xffffffffu, s, o);
        if (lane == 0) g_rspart[((size_t)bb * NBL + tj) * DD + gi0 + r] = s;
    }
    // column partial sums (mirror), off-diagonal only
    if (!isdiag && tid < 64) {
        float s = 0.f;
        #pragma unroll 8
        for (int r = 0; r < 64; r++) s += stage[r * 68 + tid];
        g_rspart[((size_t)bb * NBL + ti) * DD + gj0 + tid] = s;
    }
}

// ---------------------------------------------------------------------------
// Kernel 3: combine partials -> rowsum/D + tot/D^2 (deterministic)
// ---------------------------------------------------------------------------
__global__ void combine_kernel() {
    int b = blockIdx.x;
    __shared__ float sh[256];
    const float inv_d = 1.f / DD;
    float loc = 0.f;
    for (int i = threadIdx.x; i < DD; i += 256) {
        float s = 0.f;
        #pragma unroll
        for (int t = 0; t < NBL; t++) s += g_rspart[((size_t)b * NBL + t) * DD + i];
        g_rowsum[b * DD + i] = s * inv_d;
        loc += s;
    }
    sh[threadIdx.x] = loc;
    __syncthreads();
    #pragma unroll
    for (int o = 128; o > 0; o >>= 1) {
        if (threadIdx.x < o) sh[threadIdx.x] += sh[threadIdx.x + o];
        __syncthreads();
    }
    if (threadIdx.x == 0) g_tot[b] = sh[0] * (inv_d * inv_d);
}

// ---------------------------------------------------------------------------
// Kernel 4: centering + triu gather; flat mapping over the concatenated
// (p, 639-p) row pair (641 elements) -> ~full thread utilization.
// ---------------------------------------------------------------------------
__global__ void out_kernel(float* __restrict__ out) {
    int p = blockIdx.x;     // 0..319
    int b = blockIdx.y;
    int i0 = p, i1 = DD - 1 - p;
    int len0 = DD - i0;     // 640-p  (row i0: j in [i0, 640))
    float tot = g_tot[b];
    const float* rs = g_rowsum + b * DD;
    float s0 = tot - rs[i0];
    float s1 = tot - rs[i1];
    const float* d0 = g_dcov + ((size_t)b * DD + i0) * DD;
    const float* d1 = g_dcov + ((size_t)b * DD + i1) * DD;
    size_t base0 = (size_t)b * TRI + (size_t)i0 * DD - ((size_t)i0 * (i0 - 1)) / 2 - i0;
    size_t base1 = (size_t)b * TRI + (size_t)i1 * DD - ((size_t)i1 * (i1 - 1)) / 2 - i1;
    // total elements = len0 + (p+1) = 641
    #pragma unroll 3
    for (int t = threadIdx.x; t < DD + 1; t += 256) {
        bool r0 = (t < len0);
        int j = r0 ? (i0 + t) : (i1 + (t - len0));
        const float* dp = r0 ? d0 : d1;
        size_t bs = r0 ? base0 : base1;
        float si = r0 ? s0 : s1;
        out[bs + j] = dp[j] - rs[j] + si;
    }
}

// ---------------------------------------------------------------------------
extern "C" void kernel_launch(void* const* d_in, const int* in_sizes, int n_in,
                              void* d_out, int out_size) {
    const float* x = (const float*)d_in[0];
    float* out = (float*)d_out;

    cudaFuncSetAttribute(gram_mma_kernel,
                         cudaFuncAttributeMaxDynamicSharedMemorySize, SMEM_BYTES);

    conv_diag_kernel<<<(BB * DD) / 8, 256>>>(x);
    gram_mma_kernel<<<dim3(NTILE, BB), 128, SMEM_BYTES>>>();
    combine_kernel<<<BB, 256>>>();
    out_kernel<<<dim3(DD / 2, BB), 256>>>(out);
}

// round 16
// speedup vs baseline: 1.6019x; 1.1692x over previous
#include <cuda_runtime.h>
#include <cuda_fp16.h>
#include <cstdint>

#define BB 32
#define DD 640
#define MM 1024
#define TRI (DD*(DD+1)/2)
#define TEMPR (1.0f/(2.0f*DD*MM))
#define EPSV 1e-5f

#define NBL 10                /* 640/64 tile blocks per dim */
#define NTILE (NBL*(NBL+1)/2) /* 55 upper-tri tiles per batch */
#define KC 32                 /* f16 K per chunk; hi|lo packed -> 128B/row */
#define NCH (MM/KC)           /* 32 chunks */

// ---- device scratch (no runtime allocation) ----
// per row: 32 chunks of [hi x32 f16 | lo x32 f16]; row stride 2048 f16 = 4KB
__device__ __align__(256) __half g_hl[(size_t)BB*DD*2048];         // 83.9 MB
__device__ __align__(256) float g_dcov[(size_t)BB*DD*DD];          // upper tiles only
__device__ float g_diag[BB*DD];
__device__ float g_rspart[(size_t)BB*NBL*DD];
__device__ float g_rowsum[BB*DD];   // pre-scaled by 1/D
__device__ float g_tot[BB];         // pre-scaled by 1/D^2

// ---------------- baseline-PTX helpers ----------------
__device__ __forceinline__ uint32_t smem_u32(const void* p) {
    uint32_t a;
    asm("{ .reg .u64 t; cvta.to.shared.u64 t, %1; cvt.u32.u64 %0, t; }" : "=r"(a) : "l"(p));
    return a;
}
#define SW128(o) ((o) ^ (((o) >> 3) & 0x70))
#define SW64(o)  ((o) ^ (((o) >> 3) & 0x30))

// d = { lo16 = f16(lo), hi16 = f16(hi) }
#define CVT2F16(d, hi, lo) \
    asm("cvt.rn.f16x2.f32 %0, %1, %2;" : "=r"(d) : "f"(hi), "f"(lo))

#define CP_ASYNC16(dst, src) \
    asm volatile("cp.async.cg.shared.global [%0], [%1], 16;" :: "r"(dst), "l"(src) : "memory")
#define CP_COMMIT() asm volatile("cp.async.commit_group;" ::: "memory")
#define CP_WAIT0()  asm volatile("cp.async.wait_group 0;" ::: "memory")

#define LDSM4(r, addr) \
    asm volatile("ldmatrix.sync.aligned.m8n8.x4.shared.b16 {%0,%1,%2,%3}, [%4];" \
                 : "=r"((r)[0]), "=r"((r)[1]), "=r"((r)[2]), "=r"((r)[3]) : "r"(addr))

#define MMA_F16(c, a, b0, b1) \
    asm volatile("mma.sync.aligned.m16n8k16.row.col.f32.f16.f16.f32 " \
                 "{%0,%1,%2,%3}, {%4,%5,%6,%7}, {%8,%9}, {%0,%1,%2,%3};" \
                 : "+f"((c)[0]), "+f"((c)[1]), "+f"((c)[2]), "+f"((c)[3]) \
                 : "r"((a)[0]), "r"((a)[1]), "r"((a)[2]), "r"((a)[3]), "r"(b0), "r"(b1))

// ---------------------------------------------------------------------------
// Kernel 1: fp32 -> packed (hi|lo) f16 + diag row-norms. One warp per row.
// ---------------------------------------------------------------------------
__global__ void conv_diag_kernel(const float* __restrict__ x) {
    int w = (blockIdx.x * blockDim.x + threadIdx.x) >> 5;
    int lane = threadIdx.x & 31;
    if (w >= BB * DD) return;
    const float4* row = reinterpret_cast<const float4*>(x + (size_t)w * MM);
    __half* pr = g_hl + (size_t)w * 2048;
    float s = 0.f;
    #pragma unroll
    for (int m4 = lane; m4 < MM / 4; m4 += 32) {
        float4 v = row[m4];
        s += v.x*v.x + v.y*v.y + v.z*v.z + v.w*v.w;
        uint32_t hA, hB;
        CVT2F16(hA, v.y, v.x);      // {hi16=f16(v.y), lo16=f16(v.x)}
        CVT2F16(hB, v.w, v.z);
        float2 fA = __half22float2(*reinterpret_cast<__half2*>(&hA));
        float2 fB = __half22float2(*reinterpret_cast<__half2*>(&hB));
        uint32_t lA, lB;
        CVT2F16(lA, v.y - fA.y, v.x - fA.x);
        CVT2F16(lB, v.w - fB.y, v.z - fB.x);
        int col0 = m4 * 4;
        int kc = col0 >> 5, wi = col0 & 31;
        uint2 hp; hp.x = hA; hp.y = hB;
        uint2 lp; lp.x = lA; lp.y = lB;
        *reinterpret_cast<uint2*>(pr + kc * 64 + wi)      = hp;
        *reinterpret_cast<uint2*>(pr + kc * 64 + 32 + wi) = lp;
    }
    #pragma unroll
    for (int o = 16; o > 0; o >>= 1) s += __shfl_down_sync(0xffffffffu, s, o);
    if (lane == 0) g_diag[w] = s;
}

// ---------------------------------------------------------------------------
// Kernel 2: Gram via mma.sync f16 (hi/lo split, 2 passes: hi*hi + hi*lo),
// 64x64 tiles, 4-warp CTAs, double-buffered cp.async, 6 CTAs/SM.
// A side loads hi ONLY (SW64, 4KB); B side loads hi|lo (SW128, 8KB).
// ---------------------------------------------------------------------------
// smem: two 12KB stages (A 4K @0, B 8K @4096). Epilogue reuses as
// float stage[64][68] (17.4KB <= 24KB).
#define STAGE_BYTES 12288
#define SMEM_BYTES  24576

__device__ __forceinline__ void load_tileA(const __half* src, uint32_t dst,
                                           int kc, int tid) {
    #pragma unroll
    for (int it = 0; it < 2; it++) {
        int idx = it * 128 + tid;           // 0..255
        int row = idx >> 2, c16 = idx & 3;  // 64 rows x 4 sixteens (hi half)
        const char* s = (const char*)src + (size_t)row * 4096 + kc * 128 + c16 * 16;
        uint32_t off = (uint32_t)(row * 64 + c16 * 16);
        CP_ASYNC16(dst + SW64(off), s);
    }
}
__device__ __forceinline__ void load_tileB(const __half* src, uint32_t dst,
                                           int kc, int tid) {
    #pragma unroll
    for (int it = 0; it < 4; it++) {
        int idx = it * 128 + tid;           // 0..511
        int row = idx >> 3, c16 = idx & 7;  // 64 rows x 8 sixteens (hi|lo)
        const char* s = (const char*)src + (size_t)row * 4096 + kc * 128 + c16 * 16;
        uint32_t off = (uint32_t)(row * 128 + c16 * 16);
        CP_ASYNC16(dst + SW128(off), s);
    }
}

__global__ __launch_bounds__(128, 6) void gram_mma_kernel() {
    extern __shared__ __align__(1024) uint8_t smem[];
    uint32_t sb = smem_u32(smem);
    __shared__ float s_di[64], s_dj[64];

    int tid = threadIdx.x;
    int wid = tid >> 5, lane = tid & 31;
    int bb = blockIdx.y;

    int lin = blockIdx.x, ti = 0, rem = lin;
    while (rem >= NBL - ti) { rem -= NBL - ti; ti++; }
    int tj = ti + rem;
    bool isdiag = (ti == tj);
    int gi0 = ti * 64, gj0 = tj * 64;

    const __half* pA = g_hl + (size_t)(bb * DD + gi0) * 2048;
    const __half* pB = g_hl + (size_t)(bb * DD + gj0) * 2048;

    int wr = wid >> 1, wc = wid & 1;   // 2 x 2 warp grid; warp tile 32x32

    int a_row = lane & 15;
    int a_kb  = (lane >> 4) * 16;
    int b_row = ((lane >> 4) << 3) + (lane & 7);
    int b_kb  = ((lane >> 3) & 1) * 16;

    float acc[2][4][4];
    #pragma unroll
    for (int i = 0; i < 2; i++)
        #pragma unroll
        for (int j = 0; j < 4; j++)
            #pragma unroll
            for (int k = 0; k < 4; k++) acc[i][j][k] = 0.f;

    // preload chunk 0
    load_tileA(pA, sb, 0, tid);
    load_tileB(pB, sb + 4096, 0, tid);
    CP_COMMIT();

    for (int kc = 0; kc < NCH; kc++) {
        uint32_t cur = sb + (uint32_t)(kc & 1) * STAGE_BYTES;
        CP_WAIT0();
        __syncthreads();
        if (kc + 1 < NCH) {
            uint32_t nxt = sb + (uint32_t)((kc + 1) & 1) * STAGE_BYTES;
            load_tileA(pA, nxt, kc + 1, tid);
            load_tileB(pB, nxt + 4096, kc + 1, tid);
            CP_COMMIT();
        }
        uint32_t Ab = cur;
        uint32_t Bb = cur + 4096;
        #pragma unroll
        for (int ks = 0; ks < 2; ks++) {
            uint32_t bh[2][4], bl[2][4], ah[2][4];
            #pragma unroll
            for (int n2 = 0; n2 < 2; n2++) {
                uint32_t off = (uint32_t)((wc * 32 + n2 * 16 + b_row) * 128 + ks * 32 + b_kb);
                LDSM4(bh[n2], Bb + SW128(off));
                LDSM4(bl[n2], Bb + SW128(off + 64));
            }
            #pragma unroll
            for (int mt = 0; mt < 2; mt++) {
                uint32_t off = (uint32_t)((wr * 32 + mt * 16 + a_row) * 64 + ks * 32 + a_kb);
                LDSM4(ah[mt], Ab + SW64(off));
            }
            // pass 1: hi*hi
            #pragma unroll
            for (int mt = 0; mt < 2; mt++)
                #pragma unroll
                for (int nt = 0; nt < 4; nt++) {
                    int n2 = nt >> 1, hb = (nt & 1) * 2;
                    MMA_F16(acc[mt][nt], ah[mt], bh[n2][hb], bh[n2][hb + 1]);
                }
            // pass 2: hi*lo (B-side residual)
            #pragma unroll
            for (int mt = 0; mt < 2; mt++)
                #pragma unroll
                for (int nt = 0; nt < 4; nt++) {
                    int n2 = nt >> 1, hb = (nt & 1) * 2;
                    MMA_F16(acc[mt][nt], ah[mt], bl[n2][hb], bl[n2][hb + 1]);
                }
        }
    }

    // ---- epilogue through stage[64][68] ----
    if (tid < 64) {
        s_di[tid] = g_diag[bb * DD + gi0 + tid];
        s_dj[tid] = g_diag[bb * DD + gj0 + tid];
    }
    __syncthreads();   // all warps done with pipeline smem

    float* stage = reinterpret_cast<float*>(smem);   // [64][68]
    float* dcb = g_dcov + (size_t)bb * DD * DD;
    int qr = lane >> 2, qc = lane & 3;

    #pragma unroll
    for (int mt = 0; mt < 2; mt++) {
        int r0 = wr * 32 + mt * 16 + qr;
        float di0 = s_di[r0], di1 = s_di[r0 + 8];
        #pragma unroll
        for (int nt = 0; nt < 4; nt++) {
            int c0 = wc * 32 + nt * 8 + qc * 2;
            float dj0 = s_dj[c0], dj1 = s_dj[c0 + 1];
            float* c = acc[mt][nt];
            stage[r0 * 68 + c0]           = sqrtf(fmaf(TEMPR, fmaxf(di0 + dj0 - 2.f * c[0], 0.f), EPSV));
            stage[r0 * 68 + c0 + 1]       = sqrtf(fmaf(TEMPR, fmaxf(di0 + dj1 - 2.f * c[1], 0.f), EPSV));
            stage[(r0 + 8) * 68 + c0]     = sqrtf(fmaf(TEMPR, fmaxf(di1 + dj0 - 2.f * c[2], 0.f), EPSV));
            stage[(r0 + 8) * 68 + c0 + 1] = sqrtf(fmaf(TEMPR, fmaxf(di1 + dj1 - 2.f * c[3], 0.f), EPSV));
        }
    }
    __syncthreads();

    // coalesced dcov store: 64 x 64
    #pragma unroll
    for (int it = 0; it < 32; it++) {
        int idx = it * 128 + tid;
        int r = idx >> 6, cjj = idx & 63;
        dcb[(size_t)(gi0 + r) * DD + gj0 + cjj] = stage[r * 68 + cjj];
    }
    // row partial sums -> slot [tj]
    #pragma unroll
    for (int rr = 0; rr < 16; rr++) {
        int r = wid * 16 + rr;
        float s = stage[r * 68 + lane] + stage[r * 68 + lane + 32];
        #pragma unroll
        for (int o = 16; o > 0; o >>= 1) s += __shfl_down_sync(0xffffffffu, s, o);
        if (lane == 0) g_rspart[((size_t)bb * NBL + tj) * DD + gi0 + r] = s;
    }
    // column partial sums (mirror), off-diagonal only
    if (!isdiag && tid < 64) {
        float s = 0.f;
        #pragma unroll 8
        for (int r = 0; r < 64; r++) s += stage[r * 68 + tid];
        g_rspart[((size_t)bb * NBL + ti) * DD + gj0 + tid] = s;
    }
}

// ---------------------------------------------------------------------------
// Kernel 3: combine partials -> rowsum/D + tot/D^2 (deterministic)
// ---------------------------------------------------------------------------
__global__ void combine_kernel() {
    int b = blockIdx.x;
    __shared__ float sh[256];
    const float inv_d = 1.f / DD;
    float loc = 0.f;
    for (int i = threadIdx.x; i < DD; i += 256) {
        float s = 0.f;
        #pragma unroll
        for (int t = 0; t < NBL; t++) s += g_rspart[((size_t)b * NBL + t) * DD + i];
        g_rowsum[b * DD + i] = s * inv_d;
        loc += s;
    }
    sh[threadIdx.x] = loc;
    __syncthreads();
    #pragma unroll
    for (int o = 128; o > 0; o >>= 1) {
        if (threadIdx.x < o) sh[threadIdx.x] += sh[threadIdx.x + o];
        __syncthreads();
    }
    if (threadIdx.x == 0) g_tot[b] = sh[0] * (inv_d * inv_d);
}

// ---------------------------------------------------------------------------
// Kernel 4: centering + triu gather; flat mapping over the concatenated
// (p, 639-p) row pair (641 elements) -> ~full thread utilization.
// ---------------------------------------------------------------------------
__global__ void out_kernel(float* __restrict__ out) {
    int p = blockIdx.x;     // 0..319
    int b = blockIdx.y;
    int i0 = p, i1 = DD - 1 - p;
    int len0 = DD - i0;     // 640-p  (row i0: j in [i0, 640))
    float tot = g_tot[b];
    const float* rs = g_rowsum + b * DD;
    float s0 = tot - rs[i0];
    float s1 = tot - rs[i1];
    const float* d0 = g_dcov + ((size_t)b * DD + i0) * DD;
    const float* d1 = g_dcov + ((size_t)b * DD + i1) * DD;
    size_t base0 = (size_t)b * TRI + (size_t)i0 * DD - ((size_t)i0 * (i0 - 1)) / 2 - i0;
    size_t base1 = (size_t)b * TRI + (size_t)i1 * DD - ((size_t)i1 * (i1 - 1)) / 2 - i1;
    // total elements = len0 + (p+1) = 641
    #pragma unroll 3
    for (int t = threadIdx.x; t < DD + 1; t += 256) {
        bool r0 = (t < len0);
        int j = r0 ? (i0 + t) : (i1 + (t - len0));
        const float* dp = r0 ? d0 : d1;
        size_t bs = r0 ? base0 : base1;
        float si = r0 ? s0 : s1;
        out[bs + j] = dp[j] - rs[j] + si;
    }
}

// ---------------------------------------------------------------------------
extern "C" void kernel_launch(void* const* d_in, const int* in_sizes, int n_in,
                              void* d_out, int out_size) {
    const float* x = (const float*)d_in[0];
    float* out = (float*)d_out;

    cudaFuncSetAttribute(gram_mma_kernel,
                         cudaFuncAttributeMaxDynamicSharedMemorySize, SMEM_BYTES);

    conv_diag_kernel<<<(BB * DD) / 8, 256>>>(x);
    gram_mma_kernel<<<dim3(NTILE, BB), 128, SMEM_BYTES>>>();
    combine_kernel<<<BB, 256>>>();
    out_kernel<<<dim3(DD / 2, BB), 256>>>(out);
}